// round 16
// baseline (speedup 1.0000x reference)
#include <cuda_runtime.h>
#include <cuda_bf16.h>

// Problem constants (fixed by the reference's setup_inputs)
#define BQ 4096
#define NQ 128
#define FQ 64
#define HIST 1024      // ids in [0,1000); -1 padding handled via unsigned compare
#define TROWS 129      // counts range 0..128 inclusive
#define BPB 2          // batches per block
#define PSTRIDE 68     // padded pair-sum row stride (floats)

// MLP lookup table: T[c][g] = b2[g] + sum_f relu(c*w1[f]+b1[f]) * w2[g*F+f]
__device__ float g_table[TROWS * FQ];

// ---------------------------------------------------------------------------
// Kernel 1: parallel MLP table build (proven). 129 blocks x 256 threads, one
// row per block; all 1024 w2 float4s covered; conflict-free 17-padded
// reduction. PDL trigger after the row is written.
// ---------------------------------------------------------------------------
__global__ __launch_bounds__(256)
void build_table_kernel(const float* __restrict__ w1,
                        const float* __restrict__ b1,
                        const float* __restrict__ w2,
                        const float* __restrict__ b2) {
    __shared__ float h[FQ];
    __shared__ float p[FQ][17];   // 17-pad: conflict-free reduction reads

    const int t = threadIdx.x;
    const int c = blockIdx.x;     // count value 0..128

    if (t < FQ) h[t] = fmaxf((float)c * w1[t] + b1[t], 0.0f);  // w1 shape (F,1)
    __syncthreads();

    const float4* w2v = (const float4*)w2;
#pragma unroll
    for (int k = 0; k < 4; k++) {
        const int idx = k * 256 + t;
        const int g   = idx >> 4;
        const int f4  = (idx & 15) * 4;
        const float4 w = w2v[idx];   // coalesced
        p[g][idx & 15] = h[f4] * w.x + h[f4 + 1] * w.y
                       + h[f4 + 2] * w.z + h[f4 + 3] * w.w;
    }
    __syncthreads();

    if (t < FQ) {
        float acc = b2[t];
#pragma unroll
        for (int k = 0; k < 16; k++) acc += p[t][k];
        g_table[c * FQ + t] = acc;   // einsum 'bncf,gf->bncg' => w2[g, f]
    }
    __syncthreads();   // all g_table writes in this block precede the trigger

    asm volatile("griddepcontrol.launch_dependents;" ::: "memory");
}

// ---------------------------------------------------------------------------
// Kernel 2 (fused, PDL-dependent): TWO batches per block, grid 2048 = ~1.7
// waves at 8 blocks/SM. One 4KB hist packs both batches (8 bits each for
// b0.src / b0.dst / b1.src / b1.dst), so the per-block front (zero + atomics
// + extract + S build) is amortized over 128KB of stores instead of 64KB,
// while wave-2 blocks still start staggered to hide their fronts behind
// wave-1's draining stores.
// Fast path: both count bytes < 4  <=>  (word & 0xFCFC) == 0.
// Shared: hist 4KB + S 4.25KB + scA/scB 1KB = ~9.3KB; regs ~32.
// ---------------------------------------------------------------------------
__global__ __launch_bounds__(256)
void fused_kernel(const int* __restrict__ src,
                  const int* __restrict__ dst,
                  float* __restrict__ out) {
    __shared__ unsigned int hist[HIST];       // b0.src[0:8) b0.dst[8:16) b1.src[16:24) b1.dst[24:32)
    __shared__ float S[16 * PSTRIDE];         // S[a*4+b] = T[a] + T[b]
    __shared__ unsigned short scA[BPB][NQ];   // byte0 = c_ss, byte1 = c_sd
    __shared__ unsigned short scB[BPB][NQ];   // byte0 = c_dd, byte1 = c_ds

    const int tid  = threadIdx.x;
    const int half = tid >> 7;                // 0: src owner, 1: dst owner
    const int i    = tid & 127;               // element index

    // -- front: zero hist (1024 words = 256 uint4), load both batches' ids --
    ((uint4*)hist)[tid] = make_uint4(0u, 0u, 0u, 0u);
    int ids[BPB];
#pragma unroll
    for (int lb = 0; lb < BPB; lb++) {
        const long long b = (long long)blockIdx.x * BPB + lb;
        ids[lb] = (half == 0) ? src[b * NQ + i] : dst[b * NQ + i];
    }
    __syncthreads();

    // -- histogram atomics for both batches ---------------------------------
#pragma unroll
    for (int lb = 0; lb < BPB; lb++) {
        const int sh = lb * 16 + half * 8;
        if ((unsigned)ids[lb] < HIST) atomicAdd(&hist[ids[lb]], 1u << sh);
    }
    __syncthreads();

    // -- extract counts. Padded id (-1) -> zero counts (reference's
    //    where(pad, 0, freq); MLP(0) still applied via table row 0). --------
#pragma unroll
    for (int lb = 0; lb < BPB; lb++) {
        const unsigned h = ((unsigned)ids[lb] < HIST) ? hist[ids[lb]] : 0u;
        const unsigned srcC = (h >> (lb * 16))     & 0xFFu;   // count in src
        const unsigned dstC = (h >> (lb * 16 + 8)) & 0xFFu;   // count in dst
        if (half == 0) {
            scA[lb][i] = (unsigned short)(srcC | (dstC << 8));  // (c_ss, c_sd)
        } else {
            scB[lb][i] = (unsigned short)(dstC | (srcC << 8));  // (c_dd, c_ds)
        }
    }

    // -- table needed from here: wait (instant for later blocks), build S ---
    asm volatile("griddepcontrol.wait;" ::: "memory");
    {
        const int r = tid >> 4;               // pair -> (a = r>>2, b = r&3)
        const int q = (tid & 15) * 4;
        const float4 ta = *(const float4*)(g_table + (r >> 2) * FQ + q);
        const float4 tb = *(const float4*)(g_table + (r & 3) * FQ + q);
        float4 v;
        v.x = ta.x + tb.x; v.y = ta.y + tb.y; v.z = ta.z + tb.z; v.w = ta.w + tb.w;
        *(float4*)&S[r * PSTRIDE + q] = v;
    }
    __syncthreads();

    // -- streaming write: 2 batches x 2 halves x 2048 float4, coalesced -----
    const int g4 = (tid & 15) * 4;
    const size_t halfq = (size_t)BQ * (NQ * FQ / 4);
#pragma unroll
    for (int lb = 0; lb < BPB; lb++) {
        const size_t b = (size_t)blockIdx.x * BPB + lb;
        float4* const osrc = (float4*)out + b * (NQ * FQ / 4);
        float4* const odst = osrc + halfq;
#pragma unroll
        for (int k = 0; k < 8; k++) {
            const int lin = k * 256 + tid;
            const int ii  = lin >> 4;
            const unsigned ca = (unsigned)scA[lb][ii];   // 16 lanes broadcast
            const unsigned cb = (unsigned)scB[lb][ii];

            // src_feat = T[c_ss] + T[c_sd]
            float4 a;
            if ((ca & 0xFCFCu) == 0u) {                  // both count bytes < 4
                a = *(const float4*)&S[(((ca & 3u) << 2) | (ca >> 8)) * PSTRIDE + g4];
            } else {
                const int cx = (int)(ca & 0xFFu), cy = (int)(ca >> 8);
                const float4 u = *(const float4*)(g_table + cx * FQ + g4);
                const float4 v = *(const float4*)(g_table + cy * FQ + g4);
                a.x = u.x + v.x; a.y = u.y + v.y; a.z = u.z + v.z; a.w = u.w + v.w;
            }
            __stcs(&osrc[lin], a);

            // dst_feat = T[c_dd] + T[c_ds]
            float4 e;
            if ((cb & 0xFCFCu) == 0u) {                  // both count bytes < 4
                e = *(const float4*)&S[(((cb & 3u) << 2) | (cb >> 8)) * PSTRIDE + g4];
            } else {
                const int cz = (int)(cb & 0xFFu), cw = (int)(cb >> 8);
                const float4 u = *(const float4*)(g_table + cz * FQ + g4);
                const float4 v = *(const float4*)(g_table + cw * FQ + g4);
                e.x = u.x + v.x; e.y = u.y + v.y; e.z = u.z + v.z; e.w = u.w + v.w;
            }
            __stcs(&odst[lin], e);
        }
    }
}

// ---------------------------------------------------------------------------
// Launch. Inputs (metadata order): src_ids[B*N] i32, dst_ids[B*N] i32,
// w1[F] f32, b1[F] f32, w2[F*F] f32, b2[F] f32. Output: f32, 2*B*N*F
// (src_feat flattened, then dst_feat flattened).
// Fused kernel launched with Programmatic Dependent Launch so wave-1's
// histogram front overlaps the table-build kernel.
// ---------------------------------------------------------------------------
extern "C" void kernel_launch(void* const* d_in, const int* in_sizes, int n_in,
                              void* d_out, int out_size) {
    const int*   src = (const int*)d_in[0];
    const int*   dst = (const int*)d_in[1];
    const float* w1  = (const float*)d_in[2];
    const float* b1  = (const float*)d_in[3];
    const float* w2  = (const float*)d_in[4];
    const float* b2  = (const float*)d_in[5];
    float* out = (float*)d_out;

    build_table_kernel<<<TROWS, 256>>>(w1, b1, w2, b2);

    cudaLaunchConfig_t cfg = {};
    cfg.gridDim  = dim3(BQ / BPB);      // 2048 blocks = ~1.7 waves
    cfg.blockDim = dim3(256);
    cfg.dynamicSmemBytes = 0;
    cfg.stream = 0;  // same (legacy default) stream the harness captures
    cudaLaunchAttribute attrs[1];
    attrs[0].id = cudaLaunchAttributeProgrammaticStreamSerialization;
    attrs[0].val.programmaticStreamSerializationAllowed = 1;
    cfg.attrs = attrs;
    cfg.numAttrs = 1;
    cudaLaunchKernelEx(&cfg, fused_kernel, src, dst, out);
}

// round 17
// speedup vs baseline: 1.0684x; 1.0684x over previous
#include <cuda_runtime.h>
#include <cuda_bf16.h>

// Problem constants (fixed by the reference's setup_inputs)
#define BQ 4096
#define NQ 128
#define FQ 64
#define HIST 1024      // ids in [0,1000); -1 padding handled via unsigned compare
#define TROWS 129      // counts range 0..128 inclusive
#define PSTRIDE 68     // padded pair-sum row stride (floats)

// MLP lookup table: T[c][g] = b2[g] + sum_f relu(c*w1[f]+b1[f]) * w2[g*F+f]
__device__ float g_table[TROWS * FQ];

// ---------------------------------------------------------------------------
// Kernel 1: parallel MLP table build (proven). 129 blocks x 256 threads, one
// row per block; all 1024 w2 float4s covered; conflict-free 17-padded
// reduction. PDL trigger after the row is written.
// ---------------------------------------------------------------------------
__global__ __launch_bounds__(256)
void build_table_kernel(const float* __restrict__ w1,
                        const float* __restrict__ b1,
                        const float* __restrict__ w2,
                        const float* __restrict__ b2) {
    __shared__ float h[FQ];
    __shared__ float p[FQ][17];   // 17-pad: conflict-free reduction reads

    const int t = threadIdx.x;
    const int c = blockIdx.x;     // count value 0..128

    if (t < FQ) h[t] = fmaxf((float)c * w1[t] + b1[t], 0.0f);  // w1 shape (F,1)
    __syncthreads();

    const float4* w2v = (const float4*)w2;
#pragma unroll
    for (int k = 0; k < 4; k++) {
        const int idx = k * 256 + t;
        const int g   = idx >> 4;
        const int f4  = (idx & 15) * 4;
        const float4 w = w2v[idx];   // coalesced
        p[g][idx & 15] = h[f4] * w.x + h[f4 + 1] * w.y
                       + h[f4 + 2] * w.z + h[f4 + 3] * w.w;
    }
    __syncthreads();

    if (t < FQ) {
        float acc = b2[t];
#pragma unroll
        for (int k = 0; k < 16; k++) acc += p[t][k];
        g_table[c * FQ + t] = acc;   // einsum 'bncf,gf->bncg' => w2[g, f]
    }
    __syncthreads();   // all g_table writes in this block precede the trigger

    asm volatile("griddepcontrol.launch_dependents;" ::: "memory");
}

// ---------------------------------------------------------------------------
// Kernel 2 (fused, PDL-dependent): ONE batch per block, grid 4096 = ~3.5
// waves at 8 blocks/SM. Each block: tiny front (4KB hist zero, 1 id/thread,
// 1 atomic, 1 extract) then 64KB of streaming stores. Later waves' fronts
// execute while earlier blocks' stores drain -> only wave-1's ~0.4us front
// is exposed. (R16 measured that 2 batches/block with 1.7 waves is WORSE:
// fewer waves = less desync = more exposed front.)
// Fast path: both count bytes < 4  <=>  (word & 0xFCFC) == 0.
// Shared: hist 4KB + S 4.25KB + scA/scB 0.5KB = ~8.8KB; regs ~31.
// ---------------------------------------------------------------------------
__global__ __launch_bounds__(256)
void fused_kernel(const int* __restrict__ src,
                  const int* __restrict__ dst,
                  float* __restrict__ out) {
    __shared__ unsigned int hist[HIST];     // src count in low 16, dst in high 16
    __shared__ float S[16 * PSTRIDE];       // S[a*4+b] = T[a] + T[b]
    __shared__ unsigned short scA[NQ];      // byte0 = c_ss, byte1 = c_sd
    __shared__ unsigned short scB[NQ];      // byte0 = c_dd, byte1 = c_ds

    const int tid  = threadIdx.x;
    const int half = tid >> 7;              // 0: src owner, 1: dst owner
    const int i    = tid & 127;             // element index
    const int b    = blockIdx.x;            // batch

    // -- front: zero hist (1024 words = 256 uint4), load this thread's id ---
    ((uint4*)hist)[tid] = make_uint4(0u, 0u, 0u, 0u);
    const int id = (half == 0) ? src[b * NQ + i] : dst[b * NQ + i];
    __syncthreads();

    // -- histogram atomics ---------------------------------------------------
    if ((unsigned)id < HIST) atomicAdd(&hist[id], half ? 65536u : 1u);
    __syncthreads();

    // -- extract counts. Padded id (-1) -> zero counts (reference's
    //    where(pad, 0, freq); MLP(0) still applied via table row 0). --------
    const unsigned h = ((unsigned)id < HIST) ? hist[id] : 0u;
    if (half == 0) {
        // c_ss = low16 (count in src), c_sd = high16 (count in dst)
        scA[i] = (unsigned short)((h & 0xFFu) | ((h >> 8) & 0xFF00u));
    } else {
        // c_dd = high16 (count in dst), c_ds = low16 (count in src)
        scB[i] = (unsigned short)(((h >> 16) & 0xFFu) | ((h & 0xFFu) << 8));
    }

    // -- table needed from here: wait (instant for waves >= 2), build S ------
    asm volatile("griddepcontrol.wait;" ::: "memory");
    {
        const int r = tid >> 4;              // pair -> (a = r>>2, b = r&3)
        const int q = (tid & 15) * 4;
        const float4 ta = *(const float4*)(g_table + (r >> 2) * FQ + q);
        const float4 tb = *(const float4*)(g_table + (r & 3) * FQ + q);
        float4 v;
        v.x = ta.x + tb.x; v.y = ta.y + tb.y; v.z = ta.z + tb.z; v.w = ta.w + tb.w;
        *(float4*)&S[r * PSTRIDE + q] = v;
    }
    __syncthreads();

    // -- streaming write: 2 halves x 2048 float4, fully coalesced -----------
    const int g4 = (tid & 15) * 4;
    const size_t halfq = (size_t)BQ * (NQ * FQ / 4);
    float4* const osrc = (float4*)out + (size_t)b * (NQ * FQ / 4);
    float4* const odst = osrc + halfq;

#pragma unroll
    for (int k = 0; k < 8; k++) {
        const int lin = k * 256 + tid;
        const int ii  = lin >> 4;
        const unsigned ca = (unsigned)scA[ii];   // 16 lanes broadcast
        const unsigned cb = (unsigned)scB[ii];

        // src_feat = T[c_ss] + T[c_sd]
        float4 a;
        if ((ca & 0xFCFCu) == 0u) {              // both count bytes < 4
            a = *(const float4*)&S[(((ca & 3u) << 2) | (ca >> 8)) * PSTRIDE + g4];
        } else {
            const int cx = (int)(ca & 0xFFu), cy = (int)(ca >> 8);
            const float4 u = *(const float4*)(g_table + cx * FQ + g4);
            const float4 v = *(const float4*)(g_table + cy * FQ + g4);
            a.x = u.x + v.x; a.y = u.y + v.y; a.z = u.z + v.z; a.w = u.w + v.w;
        }
        __stcs(&osrc[lin], a);

        // dst_feat = T[c_dd] + T[c_ds]
        float4 e;
        if ((cb & 0xFCFCu) == 0u) {              // both count bytes < 4
            e = *(const float4*)&S[(((cb & 3u) << 2) | (cb >> 8)) * PSTRIDE + g4];
        } else {
            const int cz = (int)(cb & 0xFFu), cw = (int)(cb >> 8);
            const float4 u = *(const float4*)(g_table + cz * FQ + g4);
            const float4 v = *(const float4*)(g_table + cw * FQ + g4);
            e.x = u.x + v.x; e.y = u.y + v.y; e.z = u.z + v.z; e.w = u.w + v.w;
        }
        __stcs(&odst[lin], e);
    }
}

// ---------------------------------------------------------------------------
// Launch. Inputs (metadata order): src_ids[B*N] i32, dst_ids[B*N] i32,
// w1[F] f32, b1[F] f32, w2[F*F] f32, b2[F] f32. Output: f32, 2*B*N*F
// (src_feat flattened, then dst_feat flattened).
// Fused kernel launched with Programmatic Dependent Launch so wave-1's
// histogram front overlaps the table-build kernel.
// ---------------------------------------------------------------------------
extern "C" void kernel_launch(void* const* d_in, const int* in_sizes, int n_in,
                              void* d_out, int out_size) {
    const int*   src = (const int*)d_in[0];
    const int*   dst = (const int*)d_in[1];
    const float* w1  = (const float*)d_in[2];
    const float* b1  = (const float*)d_in[3];
    const float* w2  = (const float*)d_in[4];
    const float* b2  = (const float*)d_in[5];
    float* out = (float*)d_out;

    build_table_kernel<<<TROWS, 256>>>(w1, b1, w2, b2);

    cudaLaunchConfig_t cfg = {};
    cfg.gridDim  = dim3(BQ);            // one batch per block, ~3.5 waves
    cfg.blockDim = dim3(256);
    cfg.dynamicSmemBytes = 0;
    cfg.stream = 0;  // same (legacy default) stream the harness captures
    cudaLaunchAttribute attrs[1];
    attrs[0].id = cudaLaunchAttributeProgrammaticStreamSerialization;
    attrs[0].val.programmaticStreamSerializationAllowed = 1;
    cfg.attrs = attrs;
    cfg.numAttrs = 1;
    cudaLaunchKernelEx(&cfg, fused_kernel, src, dst, out);
}